// round 2
// baseline (speedup 1.0000x reference)
#include <cuda_runtime.h>
#include <cuda_bf16.h>

#define GS 32
#define NN 16
#define ATOM_TYPE 6

// out[b,a,i,j,k] = sum_{n: an[a,n]==6} exp(coeff*((ti-dx)^2+(tj-dy)^2+(tk-dz)^2))
// Separable Gaussian: ex[i]*ey[j]*ez[k]. Block = (ba, i-quarter), 256 threads.
// Thread t owns j = t>>3, k0 = (t&7)*4 -> 8 float4 register accumulators.
__global__ __launch_bounds__(256, 4) void voxel_kernel(
    const float* __restrict__ dv,     // (B, A, N, 3)
    const int*   __restrict__ an,     // (A, N) int32
    const float* __restrict__ sigma,  // (1,)
    float* __restrict__ out)          // (B, A, G, G, G)
{
    const int ba = blockIdx.x;   // b*32 + a
    const int a  = ba & 31;
    const int iq = blockIdx.y;   // i in [iq*8, iq*8+8)
    const int t  = threadIdx.x;
    const int j  = t >> 3;
    const int k0 = (t & 7) << 2;

    __shared__ float s_exi[NN][8];
    __shared__ float s_ey[NN][GS];
    __shared__ __align__(16) float s_ez[NN][GS];
    __shared__ float s_dx[NN], s_dy[NN], s_dz[NN];
    __shared__ int   s_act[NN];
    __shared__ int   s_nact;

    // Parallel mask + dv load in warp 0: an and dv LDGs issue concurrently,
    // compaction via ballot (no serial thread-0 chain).
    if (t < 32) {
        bool act = false;
        if (t < NN) {
            act = (an[a * NN + t] == ATOM_TYPE);
            const float* p = dv + ((long)ba * NN + t) * 3;
            s_dx[t] = p[0];
            s_dy[t] = p[1];
            s_dz[t] = p[2];
        }
        unsigned m = __ballot_sync(0xffffffffu, act);
        if (act) s_act[__popc(m & ((1u << t) - 1u))] = t;
        if (t == 0) s_nact = __popc(m);
    }
    __syncthreads();
    const int nact = s_nact;

    float* outp = out + (long)ba * (GS * GS * GS)
                      + (long)iq * 8 * (GS * GS)
                      + 4 * t;   // j*32 + k0 == 4*t

    if (nact == 0) {
        // Uniform fast path: write zeros, retire (no further barriers executed).
        const float4 z = make_float4(0.f, 0.f, 0.f, 0.f);
        #pragma unroll
        for (int ii = 0; ii < 8; ++ii)
            *reinterpret_cast<float4*>(outp + ii * (GS * GS)) = z;
        return;
    }

    const float sg = __ldg(sigma);
    const float coeff = -0.5f / (sg * sg);
    const float step = 8.0f / 31.0f;

    // Separable exponential factors (compact-indexed by m).
    for (int idx = t; idx < nact * GS; idx += 256) {
        const int m = idx >> 5, g = idx & 31;
        const int n = s_act[m];
        const float tick = -4.0f + (float)g * step;
        const float dyv = tick - s_dy[n];
        const float dzv = tick - s_dz[n];
        s_ey[m][g] = __expf(coeff * dyv * dyv);
        s_ez[m][g] = __expf(coeff * dzv * dzv);
    }
    for (int idx = t; idx < nact * 8; idx += 256) {
        const int m = idx >> 3, ii = idx & 7;
        const int n = s_act[m];
        const float tick = -4.0f + (float)(iq * 8 + ii) * step;
        const float dxv = tick - s_dx[n];
        s_exi[m][ii] = __expf(coeff * dxv * dxv);
    }
    __syncthreads();

    // Register accumulators for all 8 i-slices; per-m loads hoisted out of ii.
    float4 acc[8];
    #pragma unroll
    for (int ii = 0; ii < 8; ++ii) acc[ii] = make_float4(0.f, 0.f, 0.f, 0.f);

    for (int m = 0; m < nact; ++m) {
        const float eyj = s_ey[m][j];                              // broadcast LDS
        float4 ez4 = *reinterpret_cast<const float4*>(&s_ez[m][k0]);
        ez4.x *= eyj; ez4.y *= eyj; ez4.z *= eyj; ez4.w *= eyj;
        #pragma unroll
        for (int ii = 0; ii < 8; ++ii) {
            const float ex = s_exi[m][ii];                         // broadcast LDS
            acc[ii].x = fmaf(ex, ez4.x, acc[ii].x);
            acc[ii].y = fmaf(ex, ez4.y, acc[ii].y);
            acc[ii].z = fmaf(ex, ez4.z, acc[ii].z);
            acc[ii].w = fmaf(ex, ez4.w, acc[ii].w);
        }
    }

    #pragma unroll
    for (int ii = 0; ii < 8; ++ii)
        *reinterpret_cast<float4*>(outp + ii * (GS * GS)) = acc[ii];
}

extern "C" void kernel_launch(void* const* d_in, const int* in_sizes, int n_in,
                              void* d_out, int out_size) {
    const float* dv    = (const float*)d_in[0];   // distance_vector (B,32,16,3)
    const int*   an    = (const int*)d_in[1];     // atomic_numbers (32,16) int32
    const float* sigma = (const float*)d_in[2];   // (1,)
    float* out = (float*)d_out;

    const int B = in_sizes[0] / (32 * 16 * 3);    // derive batch from input size
    dim3 grid(B * 32, 4);
    voxel_kernel<<<grid, 256>>>(dv, an, sigma, out);
}

// round 3
// speedup vs baseline: 1.1144x; 1.1144x over previous
#include <cuda_runtime.h>
#include <cuda_bf16.h>

#define GS 32
#define NN 16
#define SLICES 4
#define ATOM_TYPE 6

// out[b,a,i,j,k] = sum_{n: an[a,n]==6} exp(coeff*||grid - dv||^2), separable:
// ex[i]*ey[j]*ez[k]. Block = (ba, i-octant of 4 slices), 256 threads.
// Thread t owns (j = t>>3, k0 = (t&7)*4) -> 4 float4 register accumulators.
// Single __syncthreads; per-warp ballot + __fns compaction (no shared act list).
__global__ __launch_bounds__(256) void voxel_kernel(
    const float* __restrict__ dv,     // (B, A, N, 3)
    const int*   __restrict__ an,     // (A, N) int32
    const float* __restrict__ sigma,  // (1,)
    float* __restrict__ out)          // (B, A, G, G, G)
{
    const int ba = blockIdx.x;        // b*32 + a
    const int a  = ba & 31;
    const int iq = blockIdx.y;        // slices [iq*4, iq*4+4)
    const int t  = threadIdx.x;
    const int j  = t >> 3;
    const int k0 = (t & 7) << 2;

    __shared__ float s_ey[NN][GS];
    __shared__ __align__(16) float s_ez[NN][GS];
    __shared__ float s_exi[NN][SLICES];

    // Warm L1 with this block's dv rows (concurrent with the an load below),
    // so the dependent dv reads in phase B are L1 hits, not a serial DRAM hop.
    float pf = 0.0f;
    if (t < NN * 3) pf = dv[(long)ba * (NN * 3) + t];
    asm volatile("" :: "f"(pf));  // keep the prefetch alive

    // Per-warp ballot compaction: mask/nact are warp-uniform, no shared, no barrier.
    const int lane = t & 31;
    bool act = false;
    if (lane < NN) act = (an[a * NN + lane] == ATOM_TYPE);
    const unsigned mask = __ballot_sync(0xffffffffu, act);
    const int nact = __popc(mask);

    const float sg = __ldg(sigma);
    const float coeff = -0.5f / (sg * sg);
    const float step = 8.0f / 31.0f;

    // Phase B: separable exponential factors (compact index m -> neighbor n via __fns).
    for (int idx = t; idx < nact * GS; idx += 256) {        // <= 512 items
        const int m = idx >> 5, g = idx & 31;
        const int n = (int)__fns(mask, 0, m + 1);
        const float dy = dv[((long)ba * NN + n) * 3 + 1];   // L1 hit (prefetched)
        const float dz = dv[((long)ba * NN + n) * 3 + 2];
        const float tick = -4.0f + (float)g * step;
        const float ddy = tick - dy;
        const float ddz = tick - dz;
        s_ey[m][g] = __expf(coeff * ddy * ddy);
        s_ez[m][g] = __expf(coeff * ddz * ddz);
    }
    if (t < nact * SLICES) {                                 // <= 64 items
        const int m = t >> 2, ii = t & 3;
        const int n = (int)__fns(mask, 0, m + 1);
        const float dx = dv[((long)ba * NN + n) * 3];
        const float tick = -4.0f + (float)(iq * SLICES + ii) * step;
        const float ddx = tick - dx;
        s_exi[m][ii] = __expf(coeff * ddx * ddx);
    }
    __syncthreads();

    // Accumulate: per m hoist ey[j]*ez4, then 4 slices x 4 FMA.
    float4 acc[SLICES];
    #pragma unroll
    for (int ii = 0; ii < SLICES; ++ii) acc[ii] = make_float4(0.f, 0.f, 0.f, 0.f);

    for (int m = 0; m < nact; ++m) {
        const float eyj = s_ey[m][j];                              // broadcast LDS
        float4 ez4 = *reinterpret_cast<const float4*>(&s_ez[m][k0]);
        ez4.x *= eyj; ez4.y *= eyj; ez4.z *= eyj; ez4.w *= eyj;
        #pragma unroll
        for (int ii = 0; ii < SLICES; ++ii) {
            const float ex = s_exi[m][ii];                         // broadcast LDS
            acc[ii].x = fmaf(ex, ez4.x, acc[ii].x);
            acc[ii].y = fmaf(ex, ez4.y, acc[ii].y);
            acc[ii].z = fmaf(ex, ez4.z, acc[ii].z);
            acc[ii].w = fmaf(ex, ez4.w, acc[ii].w);
        }
    }

    float* outp = out + (long)ba * (GS * GS * GS)
                      + (long)(iq * SLICES) * (GS * GS)
                      + 4 * t;   // j*32 + k0 == 4*t
    #pragma unroll
    for (int ii = 0; ii < SLICES; ++ii)
        *reinterpret_cast<float4*>(outp + ii * (GS * GS)) = acc[ii];
}

extern "C" void kernel_launch(void* const* d_in, const int* in_sizes, int n_in,
                              void* d_out, int out_size) {
    const float* dv    = (const float*)d_in[0];   // distance_vector (B,32,16,3)
    const int*   an    = (const int*)d_in[1];     // atomic_numbers (32,16) int32
    const float* sigma = (const float*)d_in[2];   // (1,)
    float* out = (float*)d_out;

    const int B = in_sizes[0] / (32 * 16 * 3);    // derive batch from input size
    dim3 grid(B * 32, GS / SLICES);               // (128, 8) = 1024 blocks
    voxel_kernel<<<grid, 256>>>(dv, an, sigma, out);
}